// round 7
// baseline (speedup 1.0000x reference)
#include <cuda_runtime.h>
#include <math.h>
#include <stdint.h>

#define NN 50000
#define EE 320000
constexpr int DN   = 256;
constexpr int DEF  = 128;
constexpr int TD   = 64;
constexpr int DEIN = 192;
constexpr int H    = 8;

// ---------------- scratch ---------------------------------------------------
__device__ float g_Q[(size_t)NN * DN];
__device__ float g_K[(size_t)NN * DN];
__device__ float g_V[(size_t)NN * DN];
__device__ float g_acc[(size_t)NN * DN];
__device__ float g_denom[(size_t)NN * H];

// ---------------- helpers ---------------------------------------------------
__device__ __forceinline__ void red_add_v4(float* p, float4 v) {
    asm volatile("red.global.add.v4.f32 [%0], {%1,%2,%3,%4};"
                 :: "l"(p), "f"(v.x), "f"(v.y), "f"(v.z), "f"(v.w) : "memory");
}
__device__ __forceinline__ void red_add_f(float* p, float v) {
    asm volatile("red.global.add.f32 [%0], %1;" :: "l"(p), "f"(v) : "memory");
}
__device__ __forceinline__ uint32_t f2tf32(float f) {
    uint32_t r; asm("cvt.rna.tf32.f32 %0, %1;" : "=r"(r) : "f"(f)); return r;
}
__device__ __forceinline__ float sel4(float4 v, int q) {
    float r = v.x;
    r = (q == 1) ? v.y : r;
    r = (q == 2) ? v.z : r;
    r = (q == 3) ? v.w : r;
    return r;
}
__device__ __forceinline__ void mma_tf32(float* c, const uint32_t* a, const uint32_t* b) {
    asm volatile(
        "mma.sync.aligned.m16n8k8.row.col.f32.tf32.tf32.f32 "
        "{%0,%1,%2,%3}, {%4,%5,%6,%7}, {%8,%9}, {%0,%1,%2,%3};"
        : "+f"(c[0]), "+f"(c[1]), "+f"(c[2]), "+f"(c[3])
        : "r"(a[0]), "r"(a[1]), "r"(a[2]), "r"(a[3]), "r"(b[0]), "r"(b[1]));
}

// ---------------- smem layout -----------------------------------------------
constexpr int SM_T  = 0;
constexpr int SM_W  = 512;
constexpr int SM_BT = 768;
constexpr int SM_A0 = 1024;
constexpr int SM_A1 = SM_A0 + 16384;
constexpr int SM_B0 = SM_A1 + 16384;
constexpr int SM_B1 = SM_B0 + 16384;
constexpr int SMEM_NODE = SM_B1 + 16384;          // 66560
constexpr int EP_STRIDE = 132;
constexpr int SMEM_EDGE = SM_A0 + 128 * EP_STRIDE * 4;  // 68608

// Fragment-layout address computation (consumer layout, unchanged)
__device__ __forceinline__ void putA(uint32_t* sA, int row, int kk, float v) {
    int r = row & 15, mt = row >> 4, ks = kk >> 3;
    int ln = (r & 7) * 4 + (kk & 3);
    int ri = (r >> 3) + 2 * ((kk >> 2) & 1);
    sA[((ks * 8 + mt) * 32 + ln) * 4 + ri] = f2tf32(v);
}
__device__ __forceinline__ void putB(uint32_t* sB, int n, int kk, float v) {
    int nt = n >> 3, ks = kk >> 3;
    int ln = (n & 7) * 4 + (kk & 3);
    int ri = (kk >> 2) & 1;
    sB[((ks * 16 + nt) * 32 + ln) * 2 + ri] = f2tf32(v);
}

// ---- conflict-free B staging: 128 n-rows x 32 kk ----
// identity: n[1:0]=lane[1:0], c4[0]=lane[2], n[3:2]=lane[4:3],
//           n[6:4]=w[2:0],    c4[2:1]=w[4:3];  store order rotated by lane[4:3]
__device__ __forceinline__ void stage_B_w(uint32_t* sB, const float* __restrict__ W,
                                          int n0, int k0, int stride) {
    int tid = threadIdx.x;
#pragma unroll
    for (int i = 0; i < 4; i++) {
        int id = tid + 256 * i;
        int lane = id & 31, w = id >> 5;
        int n  = (lane & 3) | (((lane >> 3) & 3) << 2) | ((w & 7) << 4);
        int c4 = ((lane >> 2) & 1) | ((w >> 3) << 1);
        float4 v = *(const float4*)&W[(size_t)(n0 + n) * stride + k0 + c4 * 4];
        int rot = (lane >> 3) & 3;
#pragma unroll
        for (int j = 0; j < 4; j++) {
            int q = (j + rot) & 3;
            putB(sB, n, c4 * 4 + q, sel4(v, q));
        }
    }
}

// ---- conflict-free A staging (float4 source): 128 rows x 8 c4 ----
// identity: row[3:0]=lane[3:0], c4[0]=lane[4], row[6:4]=w[2:0], c4[2:1]=w[4:3];
// store order rotated by lane[2:1]
__device__ __forceinline__ void stage_A_node(uint32_t* sA, const float* __restrict__ X,
                                             int m0, int k0) {
    int tid = threadIdx.x;
#pragma unroll
    for (int i = 0; i < 4; i++) {
        int id = tid + 256 * i;
        int lane = id & 31, w = id >> 5;
        int row = (lane & 15) | ((w & 7) << 4);
        int c4  = ((lane >> 4) & 1) | ((w >> 3) << 1);
        int node = m0 + row;
        float4 v = make_float4(0.f, 0.f, 0.f, 0.f);
        if (node < NN) v = *(const float4*)&X[(size_t)node * DN + k0 + c4 * 4];
        int rot = (lane >> 1) & 3;
#pragma unroll
        for (int j = 0; j < 4; j++) {
            int q = (j + rot) & 3;
            putA(sA, row, c4 * 4 + q, sel4(v, q));
        }
    }
}

__device__ __forceinline__ void stage_A_edge(uint32_t* sA, const char* smem,
                                             const float* __restrict__ ef,
                                             int e0, int c) {
    int tid = threadIdx.x;
    if (c < 2) {
        // cos path, conflict-free mapping:
        // kk[2:0]=lane[2:0], row[3]=lane[3], row[0]=lane[4],
        // row[2:1]=w[1:0], row[6:4]=w[4:2], kk[4:3]=w[6:5]
        const float* sT  = (const float*)(smem + SM_T);
        const float* sW  = (const float*)(smem + SM_W);
        const float* sBt = (const float*)(smem + SM_BT);
        int k0 = c * 32;
#pragma unroll
        for (int i = 0; i < 16; i++) {
            int id = tid + 256 * i;
            int lane = id & 31, w = id >> 5;
            int kk  = (lane & 7) | (((w >> 5) & 3) << 3);
            int row = ((lane >> 4) & 1) | ((w & 3) << 1)
                    | (((lane >> 3) & 1) << 3) | (((w >> 2) & 7) << 4);
            float v = cosf(sT[row] * sW[k0 + kk] + sBt[k0 + kk]);
            putA(sA, row, kk, v);
        }
    } else {
        int k0 = c * 32 - 64;
#pragma unroll
        for (int i = 0; i < 4; i++) {
            int id = tid + 256 * i;
            int lane = id & 31, w = id >> 5;
            int row = (lane & 15) | ((w & 7) << 4);
            int c4  = ((lane >> 4) & 1) | ((w >> 3) << 1);
            float4 v = *(const float4*)&ef[(size_t)(e0 + row) * DEF + k0 + c4 * 4];
            int rot = (lane >> 1) & 3;
#pragma unroll
            for (int j = 0; j < 4; j++) {
                int q = (j + rot) & 3;
                putA(sA, row, c4 * 4 + q, sel4(v, q));
            }
        }
    }
}

__device__ __forceinline__ void chunk_mma(const uint32_t* sA, const uint32_t* sB,
                                          int warpM, int warpN, int lane,
                                          float acc[2][8][4]) {
#pragma unroll
    for (int ks = 0; ks < 4; ks++) {
        uint32_t af[2][4];
#pragma unroll
        for (int m = 0; m < 2; m++)
            *(uint4*)af[m] = *(const uint4*)&sA[((ks * 8 + warpM * 2 + m) * 32 + lane) * 4];
        uint32_t bf[8][2];
#pragma unroll
        for (int j = 0; j < 8; j++)
            *(uint2*)bf[j] = *(const uint2*)&sB[((ks * 16 + warpN * 8 + j) * 32 + lane) * 2];
#pragma unroll
        for (int m = 0; m < 2; m++)
#pragma unroll
            for (int j = 0; j < 8; j++) mma_tf32(acc[m][j], af[m], bf[j]);
    }
}

// ---------------- K0: zero denom ---------------------------------------------
__global__ void k_init() {
    int i = blockIdx.x * blockDim.x + threadIdx.x;
    if (i < NN * H) g_denom[i] = 0.0f;
}

// ---------------- node GEMMs: Q,K,V,skip (V blocks also zero g_acc) ----------
__global__ __launch_bounds__(256, 2)
void k_node_mma(const float* __restrict__ X,
                const float* __restrict__ Wq, const float* __restrict__ Wk,
                const float* __restrict__ Wv, const float* __restrict__ Ws,
                const float* __restrict__ bq, const float* __restrict__ bk,
                const float* __restrict__ bv, const float* __restrict__ bs,
                float* __restrict__ out) {
    extern __shared__ char smem[];
    const int tid = threadIdx.x, wid = tid >> 5, lane = tid & 31;
    const int warpM = wid & 3, warpN = wid >> 2;
    const int m0 = blockIdx.y * 128;
    const int bx = blockIdx.x, mat = bx >> 1, n0 = (bx & 1) * 128;
    const float* W; const float* bias; float* dst;
    if      (mat == 0) { W = Wq; bias = bq; dst = g_Q; }
    else if (mat == 1) { W = Wk; bias = bk; dst = g_K; }
    else if (mat == 2) { W = Wv; bias = bv; dst = g_V; }
    else               { W = Ws; bias = bs; dst = out; }

    uint32_t* sA[2] = { (uint32_t*)(smem + SM_A0), (uint32_t*)(smem + SM_A1) };
    uint32_t* sB[2] = { (uint32_t*)(smem + SM_B0), (uint32_t*)(smem + SM_B1) };

    float acc[2][8][4] = {};

    stage_A_node(sA[0], X, m0, 0);
    stage_B_w(sB[0], W, n0, 0, DN);
    __syncthreads();

    for (int c = 0; c < 8; c++) {
        chunk_mma(sA[c & 1], sB[c & 1], warpM, warpN, lane, acc);
        if (c < 7) {
            stage_A_node(sA[(c + 1) & 1], X, m0, (c + 1) * 32);
            stage_B_w(sB[(c + 1) & 1], W, n0, (c + 1) * 32, DN);
        }
        __syncthreads();
    }

    float2 bb[8];
#pragma unroll
    for (int j = 0; j < 8; j++)
        bb[j] = *(const float2*)&bias[n0 + warpN * 64 + j * 8 + (lane & 3) * 2];
#pragma unroll
    for (int m = 0; m < 2; m++)
#pragma unroll
        for (int rv = 0; rv < 2; rv++) {
            int node = m0 + warpM * 32 + m * 16 + rv * 8 + (lane >> 2);
            if (node >= NN) continue;
            size_t off = (size_t)node * DN + n0 + warpN * 64 + (lane & 3) * 2;
            float* dp = dst + off;
#pragma unroll
            for (int j = 0; j < 8; j++) {
                float2 o = make_float2(acc[m][j][rv * 2 + 0] + bb[j].x,
                                       acc[m][j][rv * 2 + 1] + bb[j].y);
                *(float2*)(dp + j * 8) = o;
            }
            if (mat == 2) {
                float* zp = g_acc + off;
#pragma unroll
                for (int j = 0; j < 8; j++)
                    *(float2*)(zp + j * 8) = make_float2(0.f, 0.f);
            }
        }
}

// ------- edge GEMM + fused time-enc + alpha + exp + scatter-aggregate -------
__global__ __launch_bounds__(256, 2)
void k_edge_mma(const float* __restrict__ ef, const int* __restrict__ etup,
                const float* __restrict__ We, const float* __restrict__ times,
                const float* __restrict__ wt, const float* __restrict__ bt) {
    extern __shared__ char smem[];
    const int tid = threadIdx.x, wid = tid >> 5, lane = tid & 31;
    const int warpM = wid & 3, warpN = wid >> 2;
    const int e0 = blockIdx.y * 128;
    const int n0 = blockIdx.x * 128;

    if (tid < 128) ((float*)(smem + SM_T))[tid] = times[e0 + tid];
    if (tid < 64) {
        ((float*)(smem + SM_W))[tid]  = wt[tid];
        ((float*)(smem + SM_BT))[tid] = bt[tid];
    }
    __syncthreads();

    uint32_t* sA[2] = { (uint32_t*)(smem + SM_A0), (uint32_t*)(smem + SM_A1) };
    uint32_t* sB[2] = { (uint32_t*)(smem + SM_B0), (uint32_t*)(smem + SM_B1) };

    float acc[2][8][4] = {};

    stage_A_edge(sA[0], smem, ef, e0, 0);
    stage_B_w(sB[0], We, n0, 0, DEIN);
    __syncthreads();

    for (int c = 0; c < 6; c++) {
        chunk_mma(sA[c & 1], sB[c & 1], warpM, warpN, lane, acc);
        if (c < 5) {
            stage_A_edge(sA[(c + 1) & 1], smem, ef, e0, c + 1);
            stage_B_w(sB[(c + 1) & 1], We, n0, (c + 1) * 32, DEIN);
        }
        __syncthreads();
    }

    // ---- transpose acc fragments into smem ep tile ----
    float* sEp = (float*)(smem + SM_A0);
#pragma unroll
    for (int m = 0; m < 2; m++)
#pragma unroll
        for (int rv = 0; rv < 2; rv++) {
            int row = warpM * 32 + m * 16 + rv * 8 + (lane >> 2);
            int col = warpN * 64 + (lane & 3) * 2;
#pragma unroll
            for (int j = 0; j < 8; j++)
                *(float2*)&sEp[row * EP_STRIDE + col + j * 8] =
                    make_float2(acc[m][j][rv * 2 + 0], acc[m][j][rv * 2 + 1]);
        }
    __syncthreads();

    // ---- warp-per-edge epilogue, unroll 2 for gather MLP ----
    const float scale = 0.17677669529663687f;
    const int hb = (n0 >> 5) + (lane >> 3);
    const int colg = n0 + lane * 4;

    int my_sd = etup[(lane >> 4) * EE + e0 + wid * 16 + (lane & 15)];

#pragma unroll
    for (int t = 0; t < 16; t += 2) {
        int eloc0 = wid * 16 + t, eloc1 = eloc0 + 1;
        int s0 = __shfl_sync(0xffffffffu, my_sd, t);
        int d0 = __shfl_sync(0xffffffffu, my_sd, 16 + t);
        int s1 = __shfl_sync(0xffffffffu, my_sd, t + 1);
        int d1 = __shfl_sync(0xffffffffu, my_sd, 17 + t);

        float4 ep0 = *(const float4*)&sEp[eloc0 * EP_STRIDE + lane * 4];
        float4 ep1 = *(const float4*)&sEp[eloc1 * EP_STRIDE + lane * 4];
        const float4 q0 = *(const float4*)&g_Q[(size_t)d0 * DN + colg];
        const float4 k0 = *(const float4*)&g_K[(size_t)s0 * DN + colg];
        const float4 v0 = *(const float4*)&g_V[(size_t)s0 * DN + colg];
        const float4 q1 = *(const float4*)&g_Q[(size_t)d1 * DN + colg];
        const float4 k1 = *(const float4*)&g_K[(size_t)s1 * DN + colg];
        const float4 v1 = *(const float4*)&g_V[(size_t)s1 * DN + colg];

        float p0 = q0.x * (k0.x + ep0.x) + q0.y * (k0.y + ep0.y)
                 + q0.z * (k0.z + ep0.z) + q0.w * (k0.w + ep0.w);
        float p1 = q1.x * (k1.x + ep1.x) + q1.y * (k1.y + ep1.y)
                 + q1.z * (k1.z + ep1.z) + q1.w * (k1.w + ep1.w);
        p0 += __shfl_xor_sync(0xffffffffu, p0, 1);
        p1 += __shfl_xor_sync(0xffffffffu, p1, 1);
        p0 += __shfl_xor_sync(0xffffffffu, p0, 2);
        p1 += __shfl_xor_sync(0xffffffffu, p1, 2);
        p0 += __shfl_xor_sync(0xffffffffu, p0, 4);
        p1 += __shfl_xor_sync(0xffffffffu, p1, 4);
        float w0 = __expf(p0 * scale);
        float w1 = __expf(p1 * scale);

        float4 r0 = make_float4(w0 * (v0.x + ep0.x), w0 * (v0.y + ep0.y),
                                w0 * (v0.z + ep0.z), w0 * (v0.w + ep0.w));
        float4 r1 = make_float4(w1 * (v1.x + ep1.x), w1 * (v1.y + ep1.y),
                                w1 * (v1.z + ep1.z), w1 * (v1.w + ep1.w));
        red_add_v4(&g_acc[(size_t)d0 * DN + colg], r0);
        red_add_v4(&g_acc[(size_t)d1 * DN + colg], r1);
        if ((lane & 7) == 0) {
            red_add_f(&g_denom[d0 * H + hb], w0);
            red_add_f(&g_denom[d1 * H + hb], w1);
        }
    }
}

// ---------------- finalize: out = skip + acc/denom ---------------------------
__global__ __launch_bounds__(256)
void k_finalize(float* __restrict__ out) {
    int idx = blockIdx.x * blockDim.x + threadIdx.x;
    if (idx >= NN * DN / 4) return;
    int node = idx >> 6;
    int col4 = idx & 63;
    int head = col4 >> 3;
    float den = g_denom[node * H + head] + 1e-16f;
    float inv = 1.0f / den;
    float4 a = ((const float4*)g_acc)[idx];
    float4 o = ((float4*)out)[idx];
    o.x += a.x * inv; o.y += a.y * inv; o.z += a.z * inv; o.w += a.w * inv;
    ((float4*)out)[idx] = o;
}

// ---------------- launch ----------------------------------------------------
extern "C" void kernel_launch(void* const* d_in, const int* in_sizes, int n_in,
                              void* d_out, int out_size) {
    const int*   etup       = (const int*)  d_in[0];
    const float* edge_feats = (const float*)d_in[1];
    const float* times      = (const float*)d_in[2];
    const float* X          = (const float*)d_in[3];
    const float* w_time     = (const float*)d_in[4];
    const float* b_time     = (const float*)d_in[5];
    const float* Wq         = (const float*)d_in[6];
    const float* bq         = (const float*)d_in[7];
    const float* Wk         = (const float*)d_in[8];
    const float* bk         = (const float*)d_in[9];
    const float* Wv         = (const float*)d_in[10];
    const float* bv         = (const float*)d_in[11];
    const float* We         = (const float*)d_in[12];
    const float* Ws         = (const float*)d_in[13];
    const float* bs         = (const float*)d_in[14];
    float* out = (float*)d_out;

    cudaFuncSetAttribute(k_node_mma, cudaFuncAttributeMaxDynamicSharedMemorySize, SMEM_NODE);
    cudaFuncSetAttribute(k_edge_mma, cudaFuncAttributeMaxDynamicSharedMemorySize, SMEM_EDGE);

    k_init<<<(NN * H + 255) / 256, 256>>>();
    k_node_mma<<<dim3(8, (NN + 127) / 128), 256, SMEM_NODE>>>(
        X, Wq, Wk, Wv, Ws, bq, bk, bv, bs, out);
    k_edge_mma<<<dim3(2, EE / 128), 256, SMEM_EDGE>>>(
        edge_feats, etup, We, times, w_time, b_time);
    k_finalize<<<(NN * DN / 4 + 255) / 256, 256>>>(out);
}

// round 8
// speedup vs baseline: 1.0024x; 1.0024x over previous
#include <cuda_runtime.h>
#include <math.h>
#include <stdint.h>

#define NN 50000
#define EE 320000
constexpr int DN   = 256;
constexpr int DEF  = 128;
constexpr int TD   = 64;
constexpr int DEIN = 192;
constexpr int H    = 8;

// ---------------- scratch ---------------------------------------------------
__device__ float g_Q[(size_t)NN * DN];
__device__ float g_K[(size_t)NN * DN];
__device__ float g_V[(size_t)NN * DN];
__device__ float g_acc[(size_t)NN * DN];
__device__ float g_denom[(size_t)NN * H];

// ---------------- helpers ---------------------------------------------------
__device__ __forceinline__ void red_add_v4(float* p, float4 v) {
    asm volatile("red.global.add.v4.f32 [%0], {%1,%2,%3,%4};"
                 :: "l"(p), "f"(v.x), "f"(v.y), "f"(v.z), "f"(v.w) : "memory");
}
__device__ __forceinline__ void red_add_f(float* p, float v) {
    asm volatile("red.global.add.f32 [%0], %1;" :: "l"(p), "f"(v) : "memory");
}
__device__ __forceinline__ uint32_t f2tf32(float f) {
    uint32_t r; asm("cvt.rna.tf32.f32 %0, %1;" : "=r"(r) : "f"(f)); return r;
}
__device__ __forceinline__ float sel4(float4 v, int q) {
    float r = v.x;
    r = (q == 1) ? v.y : r;
    r = (q == 2) ? v.z : r;
    r = (q == 3) ? v.w : r;
    return r;
}
__device__ __forceinline__ void mma_tf32(float* c, const uint32_t* a, const uint32_t* b) {
    asm volatile(
        "mma.sync.aligned.m16n8k8.row.col.f32.tf32.tf32.f32 "
        "{%0,%1,%2,%3}, {%4,%5,%6,%7}, {%8,%9}, {%0,%1,%2,%3};"
        : "+f"(c[0]), "+f"(c[1]), "+f"(c[2]), "+f"(c[3])
        : "r"(a[0]), "r"(a[1]), "r"(a[2]), "r"(a[3]), "r"(b[0]), "r"(b[1]));
}

// ---------------- smem layout -----------------------------------------------
constexpr int SM_T  = 0;
constexpr int SM_W  = 512;
constexpr int SM_BT = 768;
constexpr int SM_A0 = 1024;
constexpr int SM_A1 = SM_A0 + 16384;
constexpr int SM_B0 = SM_A1 + 16384;
constexpr int SM_B1 = SM_B0 + 16384;
constexpr int SMEM_NODE = SM_B1 + 16384;          // 66560
constexpr int EP_STRIDE = 132;
constexpr int SMEM_EDGE = SM_A0 + 128 * EP_STRIDE * 4;  // 68608

// Fragment-layout address computation (consumer layout, unchanged)
__device__ __forceinline__ void putA(uint32_t* sA, int row, int kk, float v) {
    int r = row & 15, mt = row >> 4, ks = kk >> 3;
    int ln = (r & 7) * 4 + (kk & 3);
    int ri = (r >> 3) + 2 * ((kk >> 2) & 1);
    sA[((ks * 8 + mt) * 32 + ln) * 4 + ri] = f2tf32(v);
}
__device__ __forceinline__ void putB(uint32_t* sB, int n, int kk, float v) {
    int nt = n >> 3, ks = kk >> 3;
    int ln = (n & 7) * 4 + (kk & 3);
    int ri = (kk >> 2) & 1;
    sB[((ks * 16 + nt) * 32 + ln) * 2 + ri] = f2tf32(v);
}

// ---- B staging: R6 coalesced mapping + store-order rotation (conflict-free)
__device__ __forceinline__ void stage_B_w(uint32_t* sB, const float* __restrict__ W,
                                          int n0, int k0, int stride) {
    int tid = threadIdx.x;
    int rot = (tid >> 1) & 3;
#pragma unroll
    for (int i = 0; i < 4; i++) {
        int id = tid + 256 * i;
        int n = id >> 3, c4 = id & 7;
        float4 v = *(const float4*)&W[(size_t)(n0 + n) * stride + k0 + c4 * 4];
#pragma unroll
        for (int j = 0; j < 4; j++) {
            int q = (j + rot) & 3;
            putB(sB, n, c4 * 4 + q, sel4(v, q));
        }
    }
}

// ---- A staging: R6 coalesced mapping + rotation (2-way max)
__device__ __forceinline__ void stage_A_node(uint32_t* sA, const float* __restrict__ X,
                                             int m0, int k0) {
    int tid = threadIdx.x;
    int rot = (tid >> 1) & 3;
#pragma unroll
    for (int i = 0; i < 4; i++) {
        int id = tid + 256 * i;
        int row = id >> 3, c4 = id & 7;
        int node = m0 + row;
        float4 v = make_float4(0.f, 0.f, 0.f, 0.f);
        if (node < NN) v = *(const float4*)&X[(size_t)node * DN + k0 + c4 * 4];
#pragma unroll
        for (int j = 0; j < 4; j++) {
            int q = (j + rot) & 3;
            putA(sA, row, c4 * 4 + q, sel4(v, q));
        }
    }
}

__device__ __forceinline__ void stage_A_edge(uint32_t* sA, const char* smem,
                                             const float* __restrict__ ef,
                                             int e0, int c) {
    int tid = threadIdx.x;
    if (c < 2) {
        // cos path, conflict-free lane mapping:
        // row = lane3 | i[1:0]<<1 | lane4<<3 | w<<4 ;  kk = lane[2:0] | i[3:2]<<3
        const float* sT  = (const float*)(smem + SM_T);
        const float* sW  = (const float*)(smem + SM_W);
        const float* sBt = (const float*)(smem + SM_BT);
        int lane = tid & 31, w = tid >> 5;
        int k0 = c * 32;
#pragma unroll
        for (int i = 0; i < 16; i++) {
            int row = ((lane >> 3) & 1) | ((i & 3) << 1)
                    | (((lane >> 4) & 1) << 3) | (w << 4);
            int kk  = (lane & 7) | ((i >> 2) << 3);
            float v = cosf(sT[row] * sW[k0 + kk] + sBt[k0 + kk]);
            putA(sA, row, kk, v);
        }
    } else {
        int k0 = c * 32 - 64;
        int rot = (tid >> 1) & 3;
#pragma unroll
        for (int i = 0; i < 4; i++) {
            int id = tid + 256 * i;
            int row = id >> 3, c4 = id & 7;
            float4 v = *(const float4*)&ef[(size_t)(e0 + row) * DEF + k0 + c4 * 4];
#pragma unroll
            for (int j = 0; j < 4; j++) {
                int q = (j + rot) & 3;
                putA(sA, row, c4 * 4 + q, sel4(v, q));
            }
        }
    }
}

__device__ __forceinline__ void chunk_mma(const uint32_t* sA, const uint32_t* sB,
                                          int warpM, int warpN, int lane,
                                          float acc[2][8][4]) {
#pragma unroll
    for (int ks = 0; ks < 4; ks++) {
        uint32_t af[2][4];
#pragma unroll
        for (int m = 0; m < 2; m++)
            *(uint4*)af[m] = *(const uint4*)&sA[((ks * 8 + warpM * 2 + m) * 32 + lane) * 4];
        uint32_t bf[8][2];
#pragma unroll
        for (int j = 0; j < 8; j++)
            *(uint2*)bf[j] = *(const uint2*)&sB[((ks * 16 + warpN * 8 + j) * 32 + lane) * 2];
#pragma unroll
        for (int m = 0; m < 2; m++)
#pragma unroll
            for (int j = 0; j < 8; j++) mma_tf32(acc[m][j], af[m], bf[j]);
    }
}

// ---------------- node GEMMs: Q,K,V,skip (V blocks zero g_acc + g_denom) -----
__global__ __launch_bounds__(256, 2)
void k_node_mma(const float* __restrict__ X,
                const float* __restrict__ Wq, const float* __restrict__ Wk,
                const float* __restrict__ Wv, const float* __restrict__ Ws,
                const float* __restrict__ bq, const float* __restrict__ bk,
                const float* __restrict__ bv, const float* __restrict__ bs,
                float* __restrict__ out) {
    extern __shared__ char smem[];
    const int tid = threadIdx.x, wid = tid >> 5, lane = tid & 31;
    const int warpM = wid & 3, warpN = wid >> 2;
    const int m0 = blockIdx.y * 128;
    const int bx = blockIdx.x, mat = bx >> 1, n0 = (bx & 1) * 128;
    const float* W; const float* bias; float* dst;
    if      (mat == 0) { W = Wq; bias = bq; dst = g_Q; }
    else if (mat == 1) { W = Wk; bias = bk; dst = g_K; }
    else if (mat == 2) { W = Wv; bias = bv; dst = g_V; }
    else               { W = Ws; bias = bs; dst = out; }

    // fold denom zero-init into the (mat==2, n0==0) blocks
    if (bx == 4) {
        int i4 = m0 * 2 + tid;                 // float4 index into g_denom
        if (i4 < NN * H / 4)
            ((float4*)g_denom)[i4] = make_float4(0.f, 0.f, 0.f, 0.f);
    }

    uint32_t* sA[2] = { (uint32_t*)(smem + SM_A0), (uint32_t*)(smem + SM_A1) };
    uint32_t* sB[2] = { (uint32_t*)(smem + SM_B0), (uint32_t*)(smem + SM_B1) };

    float acc[2][8][4] = {};

    stage_A_node(sA[0], X, m0, 0);
    stage_B_w(sB[0], W, n0, 0, DN);
    __syncthreads();

    for (int c = 0; c < 8; c++) {
        chunk_mma(sA[c & 1], sB[c & 1], warpM, warpN, lane, acc);
        if (c < 7) {
            stage_A_node(sA[(c + 1) & 1], X, m0, (c + 1) * 32);
            stage_B_w(sB[(c + 1) & 1], W, n0, (c + 1) * 32, DN);
        }
        __syncthreads();
    }

    float2 bb[8];
#pragma unroll
    for (int j = 0; j < 8; j++)
        bb[j] = *(const float2*)&bias[n0 + warpN * 64 + j * 8 + (lane & 3) * 2];
#pragma unroll
    for (int m = 0; m < 2; m++)
#pragma unroll
        for (int rv = 0; rv < 2; rv++) {
            int node = m0 + warpM * 32 + m * 16 + rv * 8 + (lane >> 2);
            if (node >= NN) continue;
            size_t off = (size_t)node * DN + n0 + warpN * 64 + (lane & 3) * 2;
            float* dp = dst + off;
#pragma unroll
            for (int j = 0; j < 8; j++) {
                float2 o = make_float2(acc[m][j][rv * 2 + 0] + bb[j].x,
                                       acc[m][j][rv * 2 + 1] + bb[j].y);
                *(float2*)(dp + j * 8) = o;
            }
            if (mat == 2) {
                float* zp = g_acc + off;
#pragma unroll
                for (int j = 0; j < 8; j++)
                    *(float2*)(zp + j * 8) = make_float2(0.f, 0.f);
            }
        }
}

// ------- edge GEMM + fused time-enc + alpha + exp + scatter-aggregate -------
__global__ __launch_bounds__(256, 2)
void k_edge_mma(const float* __restrict__ ef, const int* __restrict__ etup,
                const float* __restrict__ We, const float* __restrict__ times,
                const float* __restrict__ wt, const float* __restrict__ bt) {
    extern __shared__ char smem[];
    const int tid = threadIdx.x, wid = tid >> 5, lane = tid & 31;
    const int warpM = wid & 3, warpN = wid >> 2;
    const int e0 = blockIdx.y * 128;
    const int n0 = blockIdx.x * 128;

    if (tid < 128) ((float*)(smem + SM_T))[tid] = times[e0 + tid];
    if (tid < 64) {
        ((float*)(smem + SM_W))[tid]  = wt[tid];
        ((float*)(smem + SM_BT))[tid] = bt[tid];
    }
    __syncthreads();

    uint32_t* sA[2] = { (uint32_t*)(smem + SM_A0), (uint32_t*)(smem + SM_A1) };
    uint32_t* sB[2] = { (uint32_t*)(smem + SM_B0), (uint32_t*)(smem + SM_B1) };

    float acc[2][8][4] = {};

    stage_A_edge(sA[0], smem, ef, e0, 0);
    stage_B_w(sB[0], We, n0, 0, DEIN);
    __syncthreads();

    for (int c = 0; c < 6; c++) {
        chunk_mma(sA[c & 1], sB[c & 1], warpM, warpN, lane, acc);
        if (c < 5) {
            stage_A_edge(sA[(c + 1) & 1], smem, ef, e0, c + 1);
            stage_B_w(sB[(c + 1) & 1], We, n0, (c + 1) * 32, DEIN);
        }
        __syncthreads();
    }

    // ---- transpose acc fragments into smem ep tile ----
    float* sEp = (float*)(smem + SM_A0);
#pragma unroll
    for (int m = 0; m < 2; m++)
#pragma unroll
        for (int rv = 0; rv < 2; rv++) {
            int row = warpM * 32 + m * 16 + rv * 8 + (lane >> 2);
            int col = warpN * 64 + (lane & 3) * 2;
#pragma unroll
            for (int j = 0; j < 8; j++)
                *(float2*)&sEp[row * EP_STRIDE + col + j * 8] =
                    make_float2(acc[m][j][rv * 2 + 0], acc[m][j][rv * 2 + 1]);
        }
    __syncthreads();

    // ---- warp-per-edge epilogue, unroll 2 for gather MLP ----
    const float scale = 0.17677669529663687f;
    const int hb = (n0 >> 5) + (lane >> 3);
    const int colg = n0 + lane * 4;

    int my_sd = etup[(lane >> 4) * EE + e0 + wid * 16 + (lane & 15)];

#pragma unroll
    for (int t = 0; t < 16; t += 2) {
        int eloc0 = wid * 16 + t, eloc1 = eloc0 + 1;
        int s0 = __shfl_sync(0xffffffffu, my_sd, t);
        int d0 = __shfl_sync(0xffffffffu, my_sd, 16 + t);
        int s1 = __shfl_sync(0xffffffffu, my_sd, t + 1);
        int d1 = __shfl_sync(0xffffffffu, my_sd, 17 + t);

        float4 ep0 = *(const float4*)&sEp[eloc0 * EP_STRIDE + lane * 4];
        float4 ep1 = *(const float4*)&sEp[eloc1 * EP_STRIDE + lane * 4];
        const float4 q0 = *(const float4*)&g_Q[(size_t)d0 * DN + colg];
        const float4 k0 = *(const float4*)&g_K[(size_t)s0 * DN + colg];
        const float4 v0 = *(const float4*)&g_V[(size_t)s0 * DN + colg];
        const float4 q1 = *(const float4*)&g_Q[(size_t)d1 * DN + colg];
        const float4 k1 = *(const float4*)&g_K[(size_t)s1 * DN + colg];
        const float4 v1 = *(const float4*)&g_V[(size_t)s1 * DN + colg];

        float p0 = q0.x * (k0.x + ep0.x) + q0.y * (k0.y + ep0.y)
                 + q0.z * (k0.z + ep0.z) + q0.w * (k0.w + ep0.w);
        float p1 = q1.x * (k1.x + ep1.x) + q1.y * (k1.y + ep1.y)
                 + q1.z * (k1.z + ep1.z) + q1.w * (k1.w + ep1.w);
        p0 += __shfl_xor_sync(0xffffffffu, p0, 1);
        p1 += __shfl_xor_sync(0xffffffffu, p1, 1);
        p0 += __shfl_xor_sync(0xffffffffu, p0, 2);
        p1 += __shfl_xor_sync(0xffffffffu, p1, 2);
        p0 += __shfl_xor_sync(0xffffffffu, p0, 4);
        p1 += __shfl_xor_sync(0xffffffffu, p1, 4);
        float w0 = __expf(p0 * scale);
        float w1 = __expf(p1 * scale);

        float4 r0 = make_float4(w0 * (v0.x + ep0.x), w0 * (v0.y + ep0.y),
                                w0 * (v0.z + ep0.z), w0 * (v0.w + ep0.w));
        float4 r1 = make_float4(w1 * (v1.x + ep1.x), w1 * (v1.y + ep1.y),
                                w1 * (v1.z + ep1.z), w1 * (v1.w + ep1.w));
        red_add_v4(&g_acc[(size_t)d0 * DN + colg], r0);
        red_add_v4(&g_acc[(size_t)d1 * DN + colg], r1);
        if ((lane & 7) == 0) {
            red_add_f(&g_denom[d0 * H + hb], w0);
            red_add_f(&g_denom[d1 * H + hb], w1);
        }
    }
}

// ---------------- finalize: out = skip + acc/denom ---------------------------
__global__ __launch_bounds__(256)
void k_finalize(float* __restrict__ out) {
    int idx = blockIdx.x * blockDim.x + threadIdx.x;
    if (idx >= NN * DN / 4) return;
    int node = idx >> 6;
    int col4 = idx & 63;
    int head = col4 >> 3;
    float den = g_denom[node * H + head] + 1e-16f;
    float inv = 1.0f / den;
    float4 a = ((const float4*)g_acc)[idx];
    float4 o = ((float4*)out)[idx];
    o.x += a.x * inv; o.y += a.y * inv; o.z += a.z * inv; o.w += a.w * inv;
    ((float4*)out)[idx] = o;
}

// ---------------- launch ----------------------------------------------------
extern "C" void kernel_launch(void* const* d_in, const int* in_sizes, int n_in,
                              void* d_out, int out_size) {
    const int*   etup       = (const int*)  d_in[0];
    const float* edge_feats = (const float*)d_in[1];
    const float* times      = (const float*)d_in[2];
    const float* X          = (const float*)d_in[3];
    const float* w_time     = (const float*)d_in[4];
    const float* b_time     = (const float*)d_in[5];
    const float* Wq         = (const float*)d_in[6];
    const float* bq         = (const float*)d_in[7];
    const float* Wk         = (const float*)d_in[8];
    const float* bk         = (const float*)d_in[9];
    const float* Wv         = (const float*)d_in[10];
    const float* bv         = (const float*)d_in[11];
    const float* We         = (const float*)d_in[12];
    const float* Ws         = (const float*)d_in[13];
    const float* bs         = (const float*)d_in[14];
    float* out = (float*)d_out;

    cudaFuncSetAttribute(k_node_mma, cudaFuncAttributeMaxDynamicSharedMemorySize, SMEM_NODE);
    cudaFuncSetAttribute(k_edge_mma, cudaFuncAttributeMaxDynamicSharedMemorySize, SMEM_EDGE);

    k_node_mma<<<dim3(8, (NN + 127) / 128), 256, SMEM_NODE>>>(
        X, Wq, Wk, Wv, Ws, bq, bk, bv, bs, out);
    k_edge_mma<<<dim3(2, EE / 128), 256, SMEM_EDGE>>>(
        edge_feats, etup, We, times, w_time, b_time);
    k_finalize<<<(NN * DN / 4 + 255) / 256, 256>>>(out);
}

// round 9
// speedup vs baseline: 1.3612x; 1.3580x over previous
#include <cuda_runtime.h>
#include <math.h>
#include <stdint.h>

#define NN 50000
#define EE 320000
constexpr int DN   = 256;
constexpr int DEF  = 128;
constexpr int TD   = 64;
constexpr int DEIN = 192;
constexpr int H    = 8;

// ---------------- scratch ---------------------------------------------------
__device__ float g_Q[(size_t)NN * DN];
__device__ float g_K[(size_t)NN * DN];
__device__ float g_V[(size_t)NN * DN];
__device__ float g_acc[(size_t)NN * DN];
__device__ float g_denom[(size_t)NN * H];

// ---------------- helpers ---------------------------------------------------
__device__ __forceinline__ void red_add_v4(float* p, float4 v) {
    asm volatile("red.global.add.v4.f32 [%0], {%1,%2,%3,%4};"
                 :: "l"(p), "f"(v.x), "f"(v.y), "f"(v.z), "f"(v.w) : "memory");
}
__device__ __forceinline__ void red_add_f(float* p, float v) {
    asm volatile("red.global.add.f32 [%0], %1;" :: "l"(p), "f"(v) : "memory");
}
__device__ __forceinline__ uint32_t f2tf32(float f) {
    uint32_t r; asm("cvt.rna.tf32.f32 %0, %1;" : "=r"(r) : "f"(f)); return r;
}
__device__ __forceinline__ void mma_tf32(float* c, const uint32_t* a, const uint32_t* b) {
    asm volatile(
        "mma.sync.aligned.m16n8k8.row.col.f32.tf32.tf32.f32 "
        "{%0,%1,%2,%3}, {%4,%5,%6,%7}, {%8,%9}, {%0,%1,%2,%3};"
        : "+f"(c[0]), "+f"(c[1]), "+f"(c[2]), "+f"(c[3])
        : "r"(a[0]), "r"(a[1]), "r"(a[2]), "r"(a[3]), "r"(b[0]), "r"(b[1]));
}

// ---------------- smem layout -----------------------------------------------
constexpr int SM_T  = 0;
constexpr int SM_W  = 512;
constexpr int SM_BT = 768;
constexpr int SM_A0 = 1024;
constexpr int SM_A1 = SM_A0 + 16384;
constexpr int SM_B0 = SM_A1 + 16384;
constexpr int SM_B1 = SM_B0 + 16384;
constexpr int SMEM_NODE = SM_B1 + 16384;          // 66560
constexpr int EP_STRIDE = 132;
constexpr int SMEM_EDGE = SM_A0 + 128 * EP_STRIDE * 4;  // 68608

// XOR-swap: produce w[t] = v[t ^ xr] in (w0..w3)
__device__ __forceinline__ void xorswap4(float4 v, int xr,
                                         float& w0, float& w1, float& w2, float& w3) {
    w0 = v.x; w1 = v.y; w2 = v.z; w3 = v.w;
    if (xr & 1) { float t = w0; w0 = w1; w1 = t; t = w2; w2 = w3; w3 = t; }
    if (xr & 2) { float t = w0; w0 = w2; w2 = t; t = w1; w1 = w3; w3 = t; }
}

// ---- A staging: base + immediate offsets, XOR store order (2-way max) ----
// thread owns (row = R0 + 32i, c4 = tid&7), R0 = tid>>3; addr = base + 256i + 4(t^xr)
__device__ __forceinline__ int stageA_base(int tid) {
    int R0 = tid >> 3, c4 = tid & 7;
    return (c4 >> 1) * 1024 + (R0 >> 4) * 128 + (R0 & 7) * 16
         + ((R0 >> 3) & 1) + 2 * (c4 & 1);
}
__device__ __forceinline__ void stA_store(uint32_t* sA, int base, int i, int xr, float4 v) {
    float w0, w1, w2, w3;
    xorswap4(v, xr, w0, w1, w2, w3);
    uint32_t* p = sA + base + 256 * i;
    p[4 * (0 ^ xr)] = f2tf32(w0);
    p[4 * (1 ^ xr)] = f2tf32(w1);
    p[4 * (2 ^ xr)] = f2tf32(w2);
    p[4 * (3 ^ xr)] = f2tf32(w3);
}

__device__ __forceinline__ void stage_A_node(uint32_t* sA, const float* __restrict__ X,
                                             int m0, int k0) {
    int tid = threadIdx.x;
    int xr = (tid >> 1) & 3;
    int R0 = tid >> 3, c4 = tid & 7;
    int base = stageA_base(tid);
#pragma unroll
    for (int i = 0; i < 4; i++) {
        int node = m0 + R0 + 32 * i;
        float4 v = make_float4(0.f, 0.f, 0.f, 0.f);
        if (node < NN) v = *(const float4*)&X[(size_t)node * DN + k0 + c4 * 4];
        stA_store(sA, base, i, xr, v);
    }
}

// ---- B staging: conflict-free ----
// addr = base + 256i + 2(t^xr)
__device__ __forceinline__ void stage_B_w(uint32_t* sB, const float* __restrict__ W,
                                          int n0, int k0, int stride) {
    int tid = threadIdx.x;
    int xr = (tid >> 1) & 3;
    int N0 = tid >> 3, c4 = tid & 7;
    int base = (c4 >> 1) * 1024 + (N0 >> 3) * 64 + (N0 & 7) * 8 + (c4 & 1);
#pragma unroll
    for (int i = 0; i < 4; i++) {
        int n = N0 + 32 * i;
        float4 v = *(const float4*)&W[(size_t)(n0 + n) * stride + k0 + c4 * 4];
        float w0, w1, w2, w3;
        xorswap4(v, xr, w0, w1, w2, w3);
        uint32_t* p = sB + base + 256 * i;
        p[2 * (0 ^ xr)] = f2tf32(w0);
        p[2 * (1 ^ xr)] = f2tf32(w1);
        p[2 * (2 ^ xr)] = f2tf32(w2);
        p[2 * (3 ^ xr)] = f2tf32(w3);
    }
}

// ---- edge A staging: cos path with conflict-free bijective mapping ----
__device__ __forceinline__ void stage_A_edge(uint32_t* sA, const char* smem,
                                             const float* __restrict__ ef,
                                             int e0, int c) {
    int tid = threadIdx.x;
    if (c < 2) {
        const float* sT  = (const float*)(smem + SM_T);
        const float* sW  = (const float*)(smem + SM_W);
        const float* sBt = (const float*)(smem + SM_BT);
        int lane = tid & 31, wq = tid >> 5;
        int k0 = c * 32;
        // base covers: mt=wq, r bit0=lane4, 4q=(lane&3)*4, ri=lane3+2*lane2
        int base = wq * 128 + ((lane >> 4) & 1) * 16 + (lane & 3) * 4
                 + ((lane >> 3) & 1) + 2 * ((lane >> 2) & 1);
        int rowb = ((lane >> 4) & 1) | (((lane >> 3) & 1) << 3) | (wq << 4);
        int kkb  = lane & 7;
#pragma unroll
        for (int i = 0; i < 16; i++) {
            int kk  = kkb | ((i & 3) << 3);
            int row = rowb | (((i >> 2) & 3) << 1);
            int addr = base + (i & 3) * 1024 + ((i >> 2) & 3) * 32;
            float v = cosf(sT[row] * sW[k0 + kk] + sBt[k0 + kk]);
            sA[addr] = f2tf32(v);
        }
    } else {
        int k0 = c * 32 - 64;
        int xr = (tid >> 1) & 3;
        int R0 = tid >> 3, c4 = tid & 7;
        int base = stageA_base(tid);
#pragma unroll
        for (int i = 0; i < 4; i++) {
            int row = R0 + 32 * i;
            float4 v = *(const float4*)&ef[(size_t)(e0 + row) * DEF + k0 + c4 * 4];
            stA_store(sA, base, i, xr, v);
        }
    }
}

__device__ __forceinline__ void chunk_mma(const uint32_t* sA, const uint32_t* sB,
                                          int warpM, int warpN, int lane,
                                          float acc[2][8][4]) {
#pragma unroll
    for (int ks = 0; ks < 4; ks++) {
        uint32_t af[2][4];
#pragma unroll
        for (int m = 0; m < 2; m++)
            *(uint4*)af[m] = *(const uint4*)&sA[((ks * 8 + warpM * 2 + m) * 32 + lane) * 4];
        uint32_t bf[8][2];
#pragma unroll
        for (int j = 0; j < 8; j++)
            *(uint2*)bf[j] = *(const uint2*)&sB[((ks * 16 + warpN * 8 + j) * 32 + lane) * 2];
#pragma unroll
        for (int m = 0; m < 2; m++)
#pragma unroll
            for (int j = 0; j < 8; j++) mma_tf32(acc[m][j], af[m], bf[j]);
    }
}

// ---------------- node GEMMs: Q,K,V,skip (folds g_acc + g_denom zeroing) -----
__global__ __launch_bounds__(256, 2)
void k_node_mma(const float* __restrict__ X,
                const float* __restrict__ Wq, const float* __restrict__ Wk,
                const float* __restrict__ Wv, const float* __restrict__ Ws,
                const float* __restrict__ bq, const float* __restrict__ bk,
                const float* __restrict__ bv, const float* __restrict__ bs,
                float* __restrict__ out) {
    extern __shared__ char smem[];
    const int tid = threadIdx.x, wid = tid >> 5, lane = tid & 31;
    const int warpM = wid & 3, warpN = wid >> 2;
    const int m0 = blockIdx.y * 128;
    const int bx = blockIdx.x, mat = bx >> 1, n0 = (bx & 1) * 128;
    const float* W; const float* bias; float* dst;
    if      (mat == 0) { W = Wq; bias = bq; dst = g_Q; }
    else if (mat == 1) { W = Wk; bias = bk; dst = g_K; }
    else if (mat == 2) { W = Wv; bias = bv; dst = g_V; }
    else               { W = Ws; bias = bs; dst = out; }

    if (bx == 4) {
        int i4 = m0 * 2 + tid;
        if (i4 < NN * H / 4)
            ((float4*)g_denom)[i4] = make_float4(0.f, 0.f, 0.f, 0.f);
    }

    uint32_t* sA[2] = { (uint32_t*)(smem + SM_A0), (uint32_t*)(smem + SM_A1) };
    uint32_t* sB[2] = { (uint32_t*)(smem + SM_B0), (uint32_t*)(smem + SM_B1) };

    float acc[2][8][4] = {};

    stage_A_node(sA[0], X, m0, 0);
    stage_B_w(sB[0], W, n0, 0, DN);
    __syncthreads();

    for (int c = 0; c < 8; c++) {
        chunk_mma(sA[c & 1], sB[c & 1], warpM, warpN, lane, acc);
        if (c < 7) {
            stage_A_node(sA[(c + 1) & 1], X, m0, (c + 1) * 32);
            stage_B_w(sB[(c + 1) & 1], W, n0, (c + 1) * 32, DN);
        }
        __syncthreads();
    }

    float2 bb[8];
#pragma unroll
    for (int j = 0; j < 8; j++)
        bb[j] = *(const float2*)&bias[n0 + warpN * 64 + j * 8 + (lane & 3) * 2];
#pragma unroll
    for (int m = 0; m < 2; m++)
#pragma unroll
        for (int rv = 0; rv < 2; rv++) {
            int node = m0 + warpM * 32 + m * 16 + rv * 8 + (lane >> 2);
            if (node >= NN) continue;
            size_t off = (size_t)node * DN + n0 + warpN * 64 + (lane & 3) * 2;
            float* dp = dst + off;
#pragma unroll
            for (int j = 0; j < 8; j++) {
                float2 o = make_float2(acc[m][j][rv * 2 + 0] + bb[j].x,
                                       acc[m][j][rv * 2 + 1] + bb[j].y);
                *(float2*)(dp + j * 8) = o;
            }
            if (mat == 2) {
                float* zp = g_acc + off;
#pragma unroll
                for (int j = 0; j < 8; j++)
                    *(float2*)(zp + j * 8) = make_float2(0.f, 0.f);
            }
        }
}

// ------- edge GEMM + fused time-enc + alpha + exp + scatter-aggregate -------
__global__ __launch_bounds__(256, 2)
void k_edge_mma(const float* __restrict__ ef, const int* __restrict__ etup,
                const float* __restrict__ We, const float* __restrict__ times,
                const float* __restrict__ wt, const float* __restrict__ bt) {
    extern __shared__ char smem[];
    const int tid = threadIdx.x, wid = tid >> 5, lane = tid & 31;
    const int warpM = wid & 3, warpN = wid >> 2;
    const int e0 = blockIdx.y * 128;
    const int n0 = blockIdx.x * 128;

    if (tid < 128) ((float*)(smem + SM_T))[tid] = times[e0 + tid];
    if (tid < 64) {
        ((float*)(smem + SM_W))[tid]  = wt[tid];
        ((float*)(smem + SM_BT))[tid] = bt[tid];
    }
    __syncthreads();

    uint32_t* sA[2] = { (uint32_t*)(smem + SM_A0), (uint32_t*)(smem + SM_A1) };
    uint32_t* sB[2] = { (uint32_t*)(smem + SM_B0), (uint32_t*)(smem + SM_B1) };

    float acc[2][8][4] = {};

    stage_A_edge(sA[0], smem, ef, e0, 0);
    stage_B_w(sB[0], We, n0, 0, DEIN);
    __syncthreads();

    for (int c = 0; c < 6; c++) {
        chunk_mma(sA[c & 1], sB[c & 1], warpM, warpN, lane, acc);
        if (c < 5) {
            stage_A_edge(sA[(c + 1) & 1], smem, ef, e0, c + 1);
            stage_B_w(sB[(c + 1) & 1], We, n0, (c + 1) * 32, DEIN);
        }
        __syncthreads();
    }

    // ---- transpose acc fragments into smem ep tile ----
    float* sEp = (float*)(smem + SM_A0);
#pragma unroll
    for (int m = 0; m < 2; m++)
#pragma unroll
        for (int rv = 0; rv < 2; rv++) {
            int row = warpM * 32 + m * 16 + rv * 8 + (lane >> 2);
            int col = warpN * 64 + (lane & 3) * 2;
#pragma unroll
            for (int j = 0; j < 8; j++)
                *(float2*)&sEp[row * EP_STRIDE + col + j * 8] =
                    make_float2(acc[m][j][rv * 2 + 0], acc[m][j][rv * 2 + 1]);
        }
    __syncthreads();

    // ---- warp-per-edge epilogue, unroll 2 for gather MLP ----
    const float scale = 0.17677669529663687f;
    const int hb = (n0 >> 5) + (lane >> 3);
    const int colg = n0 + lane * 4;

    int my_sd = etup[(lane >> 4) * EE + e0 + wid * 16 + (lane & 15)];

#pragma unroll
    for (int t = 0; t < 16; t += 2) {
        int eloc0 = wid * 16 + t, eloc1 = eloc0 + 1;
        int s0 = __shfl_sync(0xffffffffu, my_sd, t);
        int d0 = __shfl_sync(0xffffffffu, my_sd, 16 + t);
        int s1 = __shfl_sync(0xffffffffu, my_sd, t + 1);
        int d1 = __shfl_sync(0xffffffffu, my_sd, 17 + t);

        float4 ep0 = *(const float4*)&sEp[eloc0 * EP_STRIDE + lane * 4];
        float4 ep1 = *(const float4*)&sEp[eloc1 * EP_STRIDE + lane * 4];
        const float4 q0 = *(const float4*)&g_Q[(size_t)d0 * DN + colg];
        const float4 k0 = *(const float4*)&g_K[(size_t)s0 * DN + colg];
        const float4 v0 = *(const float4*)&g_V[(size_t)s0 * DN + colg];
        const float4 q1 = *(const float4*)&g_Q[(size_t)d1 * DN + colg];
        const float4 k1 = *(const float4*)&g_K[(size_t)s1 * DN + colg];
        const float4 v1 = *(const float4*)&g_V[(size_t)s1 * DN + colg];

        float p0 = q0.x * (k0.x + ep0.x) + q0.y * (k0.y + ep0.y)
                 + q0.z * (k0.z + ep0.z) + q0.w * (k0.w + ep0.w);
        float p1 = q1.x * (k1.x + ep1.x) + q1.y * (k1.y + ep1.y)
                 + q1.z * (k1.z + ep1.z) + q1.w * (k1.w + ep1.w);
        p0 += __shfl_xor_sync(0xffffffffu, p0, 1);
        p1 += __shfl_xor_sync(0xffffffffu, p1, 1);
        p0 += __shfl_xor_sync(0xffffffffu, p0, 2);
        p1 += __shfl_xor_sync(0xffffffffu, p1, 2);
        p0 += __shfl_xor_sync(0xffffffffu, p0, 4);
        p1 += __shfl_xor_sync(0xffffffffu, p1, 4);
        float w0 = __expf(p0 * scale);
        float w1 = __expf(p1 * scale);

        float4 r0 = make_float4(w0 * (v0.x + ep0.x), w0 * (v0.y + ep0.y),
                                w0 * (v0.z + ep0.z), w0 * (v0.w + ep0.w));
        float4 r1 = make_float4(w1 * (v1.x + ep1.x), w1 * (v1.y + ep1.y),
                                w1 * (v1.z + ep1.z), w1 * (v1.w + ep1.w));
        red_add_v4(&g_acc[(size_t)d0 * DN + colg], r0);
        red_add_v4(&g_acc[(size_t)d1 * DN + colg], r1);
        if ((lane & 7) == 0) {
            red_add_f(&g_denom[d0 * H + hb], w0);
            red_add_f(&g_denom[d1 * H + hb], w1);
        }
    }
}

// ---------------- finalize: out = skip + acc/denom ---------------------------
__global__ __launch_bounds__(256)
void k_finalize(float* __restrict__ out) {
    int idx = blockIdx.x * blockDim.x + threadIdx.x;
    if (idx >= NN * DN / 4) return;
    int node = idx >> 6;
    int col4 = idx & 63;
    int head = col4 >> 3;
    float den = g_denom[node * H + head] + 1e-16f;
    float inv = 1.0f / den;
    float4 a = ((const float4*)g_acc)[idx];
    float4 o = ((float4*)out)[idx];
    o.x += a.x * inv; o.y += a.y * inv; o.z += a.z * inv; o.w += a.w * inv;
    ((float4*)out)[idx] = o;
}

// ---------------- launch ----------------------------------------------------
extern "C" void kernel_launch(void* const* d_in, const int* in_sizes, int n_in,
                              void* d_out, int out_size) {
    const int*   etup       = (const int*)  d_in[0];
    const float* edge_feats = (const float*)d_in[1];
    const float* times      = (const float*)d_in[2];
    const float* X          = (const float*)d_in[3];
    const float* w_time     = (const float*)d_in[4];
    const float* b_time     = (const float*)d_in[5];
    const float* Wq         = (const float*)d_in[6];
    const float* bq         = (const float*)d_in[7];
    const float* Wk         = (const float*)d_in[8];
    const float* bk         = (const float*)d_in[9];
    const float* Wv         = (const float*)d_in[10];
    const float* bv         = (const float*)d_in[11];
    const float* We         = (const float*)d_in[12];
    const float* Ws         = (const float*)d_in[13];
    const float* bs         = (const float*)d_in[14];
    float* out = (float*)d_out;

    cudaFuncSetAttribute(k_node_mma, cudaFuncAttributeMaxDynamicSharedMemorySize, SMEM_NODE);
    cudaFuncSetAttribute(k_edge_mma, cudaFuncAttributeMaxDynamicSharedMemorySize, SMEM_EDGE);

    k_node_mma<<<dim3(8, (NN + 127) / 128), 256, SMEM_NODE>>>(
        X, Wq, Wk, Wv, Ws, bq, bk, bv, bs, out);
    k_edge_mma<<<dim3(2, EE / 128), 256, SMEM_EDGE>>>(
        edge_feats, etup, We, times, w_time, b_time);
    k_finalize<<<(NN * DN / 4 + 255) / 256, 256>>>(out);
}